// round 7
// baseline (speedup 1.0000x reference)
#include <cuda_runtime.h>
#include <cuda_fp16.h>
#include <cstdint>
#include <math.h>

#define D_MODEL 1024
#define D_FF    4096
#define NEXP    8
#define MAXN    8192
#define HROWS   (2*MAXN + 256)

#define BM 128
#define BN 128
#define BK 64                      // halfs per stage along K (128 B per A row)
#define NTHREADS 128
#define A_STRIDE_B 144             // 128 data + 16 pad
#define A_TILE_B (BM * A_STRIDE_B) // 18432
#define B_ROW_B  (BN * 2)          // 256 bytes per k-row (16 chunks)
#define B_TILE_B (BK * B_ROW_B)    // 16384
#define STAGE_B  (A_TILE_B + B_TILE_B)   // 34816
#define NSTAGE 3
#define DSMEM_BYTES (NSTAGE * STAGE_B)   // 104448 -> 2 CTAs/SM (208896 < 233472)

// ---------------- scratch (static device globals; no allocation) ----------------
__device__ int    g_cnt[NEXP];
__device__ int    g_base[NEXP];
__device__ int    g_tok[NEXP * MAXN];
__device__ float  g_gate[NEXP * MAXN];
__device__ __half g_xh [(size_t)MAXN * D_MODEL];
__device__ __half g_W1h[(size_t)NEXP * D_MODEL * D_FF];
__device__ __half g_W2h[(size_t)NEXP * D_FF * D_MODEL];
__device__ __half g_Hh [(size_t)HROWS * D_FF];

// ---------------- helpers ----------------
__device__ __forceinline__ void mma_f16(float c[4], const uint32_t a[4], const uint32_t b[2]) {
    asm volatile(
        "mma.sync.aligned.m16n8k16.row.col.f32.f16.f16.f32 "
        "{%0,%1,%2,%3}, {%4,%5,%6,%7}, {%8,%9}, {%0,%1,%2,%3};"
        : "+f"(c[0]), "+f"(c[1]), "+f"(c[2]), "+f"(c[3])
        : "r"(a[0]), "r"(a[1]), "r"(a[2]), "r"(a[3]), "r"(b[0]), "r"(b[1]));
}
__device__ __forceinline__ void ldsm_x4(uint32_t& r0, uint32_t& r1, uint32_t& r2, uint32_t& r3,
                                        uint32_t saddr) {
    asm volatile("ldmatrix.sync.aligned.m8n8.x4.shared.b16 {%0,%1,%2,%3}, [%4];"
                 : "=r"(r0), "=r"(r1), "=r"(r2), "=r"(r3) : "r"(saddr));
}
__device__ __forceinline__ void ldsm_x4_t(uint32_t& r0, uint32_t& r1, uint32_t& r2, uint32_t& r3,
                                          uint32_t saddr) {
    asm volatile("ldmatrix.sync.aligned.m8n8.x4.trans.shared.b16 {%0,%1,%2,%3}, [%4];"
                 : "=r"(r0), "=r"(r1), "=r"(r2), "=r"(r3) : "r"(saddr));
}
__device__ __forceinline__ void cp16(uint32_t saddr, const void* g) {
    asm volatile("cp.async.cg.shared.global [%0], [%1], 16;" :: "r"(saddr), "l"(g) : "memory");
}
__device__ __forceinline__ void cp_commit() { asm volatile("cp.async.commit_group;" ::: "memory"); }
__device__ __forceinline__ void cp_wait1()  { asm volatile("cp.async.wait_group 1;" ::: "memory"); }

__device__ __forceinline__ float gelu_exact(float v) {
    return 0.5f * v * (1.0f + erff(v * 0.7071067811865476f));
}

// ---------------- tiny init: counters only ----------------
__global__ void init_kernel() {
    if (threadIdx.x < NEXP) g_cnt[threadIdx.x] = 0;
}

// ---------------- fused prep: router | zero out | half x | half W1/W2 ----------------
// block ranges: [0,1024) router, [1024,1536) zero, [1536,2048) half_x, [2048,6144) half_w
__global__ void prep_kernel(float* __restrict__ out, int nout,
                            const float* __restrict__ x, int N,
                            const float* __restrict__ Wr, const float* __restrict__ br,
                            const float* __restrict__ W1, const float* __restrict__ W2) {
    const int b = blockIdx.x;
    const int tid = threadIdx.x;

    if (b < 1024) {
        // ---- router: 8 warps per block, 1 token per warp ----
        int wg = b * 8 + (tid >> 5);
        int lane = tid & 31;
        if (wg >= N) return;
        const float* xr = x + (size_t)wg * D_MODEL;

        float acc[NEXP];
#pragma unroll
        for (int e = 0; e < NEXP; e++) acc[e] = 0.0f;
#pragma unroll
        for (int it = 0; it < D_MODEL / 128; it++) {
            int d = it * 128 + lane * 4;
            float4 xv = *reinterpret_cast<const float4*>(xr + d);
            const float xa[4] = { xv.x, xv.y, xv.z, xv.w };
#pragma unroll
            for (int q = 0; q < 4; q++) {
                const float4* w4 = reinterpret_cast<const float4*>(Wr + (size_t)(d + q) * NEXP);
                float4 w0 = w4[0], w1 = w4[1];
                acc[0] += xa[q] * w0.x; acc[1] += xa[q] * w0.y;
                acc[2] += xa[q] * w0.z; acc[3] += xa[q] * w0.w;
                acc[4] += xa[q] * w1.x; acc[5] += xa[q] * w1.y;
                acc[6] += xa[q] * w1.z; acc[7] += xa[q] * w1.w;
            }
        }
#pragma unroll
        for (int off = 16; off; off >>= 1)
#pragma unroll
            for (int e = 0; e < NEXP; e++)
                acc[e] += __shfl_xor_sync(0xffffffffu, acc[e], off);

        if (lane == 0) {
            float l[NEXP];
#pragma unroll
            for (int e = 0; e < NEXP; e++) l[e] = acc[e] + br[e];
            float m = l[0];
#pragma unroll
            for (int e = 1; e < NEXP; e++) m = fmaxf(m, l[e]);
            float p[NEXP], se = 0.0f;
#pragma unroll
            for (int e = 0; e < NEXP; e++) { p[e] = expf(l[e] - m); se += p[e]; }
            int i1 = 0; float v1 = p[0];
#pragma unroll
            for (int e = 1; e < NEXP; e++) if (p[e] > v1) { v1 = p[e]; i1 = e; }
            int i2 = -1; float v2 = -1.0f;
#pragma unroll
            for (int e = 0; e < NEXP; e++) if (e != i1 && p[e] > v2) { v2 = p[e]; i2 = e; }
            float p1 = v1 / se, p2 = v2 / se;
            float inv = 1.0f / (p1 + p2 + 1e-9f);
            float w1 = p1 * inv, w2 = p2 * inv;

            int pos = atomicAdd(&g_cnt[i1], 1);
            g_tok[i1 * MAXN + pos] = wg;  g_gate[i1 * MAXN + pos] = w1;
            pos = atomicAdd(&g_cnt[i2], 1);
            g_tok[i2 * MAXN + pos] = wg;  g_gate[i2 * MAXN + pos] = w2;
        }
    } else if (b < 1536) {
        // ---- zero output (float4 grid-stride over 512 blocks) ----
        int n4 = nout >> 2;
        float4 z = make_float4(0.f, 0.f, 0.f, 0.f);
        for (int i = (b - 1024) * 256 + tid; i < n4; i += 512 * 256)
            reinterpret_cast<float4*>(out)[i] = z;
    } else if (b < 2048) {
        // ---- x -> half ----
        int n4 = N * D_MODEL / 4;
        for (int i = (b - 1536) * 256 + tid; i < n4; i += 512 * 256) {
            float4 v = reinterpret_cast<const float4*>(x)[i];
            __half2 h0 = __floats2half2_rn(v.x, v.y);
            __half2 h1 = __floats2half2_rn(v.z, v.w);
            uint2 u = { *(uint32_t*)&h0, *(uint32_t*)&h1 };
            reinterpret_cast<uint2*>(g_xh)[i] = u;
        }
    } else {
        // ---- W1, W2 -> half (4096 blocks) ----
        const int n4 = NEXP * D_MODEL * D_FF / 4;
        for (int i = (b - 2048) * 256 + tid; i < n4; i += 4096 * 256) {
            float4 v = reinterpret_cast<const float4*>(W1)[i];
            __half2 a0 = __floats2half2_rn(v.x, v.y);
            __half2 a1 = __floats2half2_rn(v.z, v.w);
            uint2 u = { *(uint32_t*)&a0, *(uint32_t*)&a1 };
            reinterpret_cast<uint2*>(g_W1h)[i] = u;
            float4 w = reinterpret_cast<const float4*>(W2)[i];
            __half2 b0 = __floats2half2_rn(w.x, w.y);
            __half2 b1 = __floats2half2_rn(w.z, w.w);
            uint2 t = { *(uint32_t*)&b0, *(uint32_t*)&b1 };
            reinterpret_cast<uint2*>(g_W2h)[i] = t;
        }
    }
}

__global__ void scan_kernel() {
    int b = 0;
#pragma unroll
    for (int e = 0; e < NEXP; e++) { g_base[e] = b; b += g_cnt[e]; }
}

// ---------------- grouped GEMM (fp16 mma.m16n8k16, CTA 128x128, 4 warps, BK=64, 3 stages) ----------------
template<int KD, int ND, bool PHASE1>
__global__ void __launch_bounds__(NTHREADS, 2)
moe_gemm_kernel(const float* __restrict__ bias, float* __restrict__ Out) {
    const int e  = blockIdx.z;
    const int Me = g_cnt[e];
    const int tm = blockIdx.y;
    if (tm * BM >= Me) return;
    const int tn   = blockIdx.x;
    const int base = g_base[e];

    extern __shared__ char smem[];
    const uint32_t sbase = (uint32_t)__cvta_generic_to_shared(smem);

    const int tid = threadIdx.x;
    const __half* Aglob = PHASE1 ? g_xh : g_Hh;
    const __half* We    = (PHASE1 ? g_W1h : g_W2h) + (size_t)e * KD * ND;

    // ---- A loader: 8 chunks of 16B per thread (128 rows x 8 chunks). row = tid/8 + 16j
    const __half* agp[8];
    {
        const int ch = tid & 7;
#pragma unroll
        for (int j = 0; j < 8; j++) {
            int row = (tid >> 3) + 16 * j;
            int m = tm * BM + row;
            size_t arow;
            if (PHASE1) arow = (size_t)g_tok[e * MAXN + (m < Me ? m : 0)];
            else { long r = (long)base + m; if (r >= HROWS) r = 0; arow = (size_t)r; }
            agp[j] = Aglob + arow * KD + ch * 8;
        }
    }
    const uint32_t aso0 = (tid >> 3) * A_STRIDE_B + (tid & 7) * 16;   // +j*16*144
    // ---- B loader: 8 chunks of 16B per thread (64 krows x 16 chunks). krow = tid/16 + 8j
    const __half* bg0 = We + (size_t)(tid >> 4) * ND + tn * BN + (tid & 15) * 8;
    const uint32_t bso0 = A_TILE_B + (tid >> 4) * B_ROW_B
                        + (((tid & 15) ^ ((tid >> 4) & 7)) << 4);     // +j*8*256 (krow&7 invariant)

    constexpr int KT = KD / BK;
    const int warp = tid >> 5, lane = tid & 31;
    const int wr = warp >> 1, wc = warp & 1;   // 2x2 warp grid; warp tile 64x64

    // ldmatrix smem addresses (stage-relative)
    uint32_t a_addr[4];  // per mt, ks adds 32 bytes each
#pragma unroll
    for (int mt = 0; mt < 4; mt++) {
        int row = wr * 64 + mt * 16 + (lane & 15);
        a_addr[mt] = row * A_STRIDE_B + (lane >> 4) * 16;
    }
    uint32_t b_addr[4][4]; // [ks][nb]
#pragma unroll
    for (int ks = 0; ks < 4; ks++)
#pragma unroll
        for (int nb = 0; nb < 4; nb++) {
            int krow = ks * 16 + (lane & 15);
            int nc = wc * 8 + nb * 2 + (lane >> 4);
            b_addr[ks][nb] = A_TILE_B + krow * B_ROW_B + ((nc ^ (krow & 7)) << 4);
        }

    float c[4][8][4];
#pragma unroll
    for (int i = 0; i < 4; i++)
#pragma unroll
        for (int j = 0; j < 8; j++)
#pragma unroll
            for (int k = 0; k < 4; k++) c[i][j][k] = 0.0f;

    // prologue: stages 0..1
#pragma unroll
    for (int s = 0; s < NSTAGE - 1; s++) {
        uint32_t sb = sbase + s * STAGE_B;
        size_t ko = (size_t)s * BK;
#pragma unroll
        for (int j = 0; j < 8; j++) cp16(sb + aso0 + j * (16 * A_STRIDE_B), agp[j] + ko);
#pragma unroll
        for (int j = 0; j < 8; j++) cp16(sb + bso0 + j * (8 * B_ROW_B), bg0 + ko * ND + (size_t)j * 8 * ND);
        cp_commit();
    }

    int buf = 0;
    for (int kt = 0; kt < KT; kt++) {
        cp_wait1();
        __syncthreads();
        {
            if (kt + NSTAGE - 1 < KT) {
                int st = buf + (NSTAGE - 1); if (st >= NSTAGE) st -= NSTAGE;
                size_t ko = (size_t)(kt + NSTAGE - 1) * BK;
                uint32_t sb = sbase + st * STAGE_B;
#pragma unroll
                for (int j = 0; j < 8; j++) cp16(sb + aso0 + j * (16 * A_STRIDE_B), agp[j] + ko);
#pragma unroll
                for (int j = 0; j < 8; j++) cp16(sb + bso0 + j * (8 * B_ROW_B), bg0 + ko * ND + (size_t)j * 8 * ND);
            }
            cp_commit();
        }
        const uint32_t sb = sbase + buf * STAGE_B;
#pragma unroll
        for (int ks = 0; ks < 4; ks++) {
            uint32_t af[4][4];
#pragma unroll
            for (int mt = 0; mt < 4; mt++)
                ldsm_x4(af[mt][0], af[mt][1], af[mt][2], af[mt][3],
                        sb + a_addr[mt] + ks * 32);
            uint32_t bf[4][4];
#pragma unroll
            for (int nb = 0; nb < 4; nb++)
                ldsm_x4_t(bf[nb][0], bf[nb][1], bf[nb][2], bf[nb][3],
                          sb + b_addr[ks][nb]);
#pragma unroll
            for (int mt = 0; mt < 4; mt++)
#pragma unroll
                for (int nb = 0; nb < 4; nb++) {
                    mma_f16(c[mt][nb * 2 + 0], af[mt], &bf[nb][0]);
                    mma_f16(c[mt][nb * 2 + 1], af[mt], &bf[nb][2]);
                }
        }
        if (++buf == NSTAGE) buf = 0;
    }

    // ---- epilogue ----
    const float* be = bias + (size_t)e * ND;
    const int bofs = tn * BN;
#pragma unroll
    for (int mt = 0; mt < 4; mt++) {
        int mrow = tm * BM + wr * 64 + mt * 16 + (lane >> 2);
#pragma unroll
        for (int half = 0; half < 2; half++) {
            int m = mrow + half * 8;
            if (m >= Me) continue;
            if (PHASE1) {
                __half* Hr = g_Hh + (size_t)(base + m) * ND + bofs;
#pragma unroll
                for (int nt = 0; nt < 8; nt++) {
                    int n = wc * 64 + nt * 8 + (lane & 3) * 2;
                    float v0 = c[mt][nt][half * 2 + 0] + be[bofs + n];
                    float v1 = c[mt][nt][half * 2 + 1] + be[bofs + n + 1];
                    __half2 h = __floats2half2_rn(gelu_exact(v0), gelu_exact(v1));
                    *reinterpret_cast<uint32_t*>(Hr + n) = *(uint32_t*)&h;
                }
            } else {
                int tok = g_tok[e * MAXN + m];
                float g = g_gate[e * MAXN + m];
                float* Or = Out + (size_t)tok * ND + bofs;
#pragma unroll
                for (int nt = 0; nt < 8; nt++) {
                    int n = wc * 64 + nt * 8 + (lane & 3) * 2;
                    atomicAdd(&Or[n],     g * (c[mt][nt][half * 2 + 0] + be[bofs + n]));
                    atomicAdd(&Or[n + 1], g * (c[mt][nt][half * 2 + 1] + be[bofs + n + 1]));
                }
            }
        }
    }
}

// ---------------- launch ----------------
extern "C" void kernel_launch(void* const* d_in, const int* in_sizes, int n_in,
                              void* d_out, int out_size) {
    const float* x  = (const float*)d_in[0];
    const float* Wr = (const float*)d_in[1];
    const float* br = (const float*)d_in[2];
    const float* W1 = (const float*)d_in[3];
    const float* b1 = (const float*)d_in[4];
    const float* W2 = (const float*)d_in[5];
    const float* b2 = (const float*)d_in[6];
    float* out = (float*)d_out;

    int N = in_sizes[0] / D_MODEL;   // 8192 tokens
    if (N > MAXN) N = MAXN;

    cudaFuncSetAttribute(moe_gemm_kernel<D_MODEL, D_FF, true>,
                         cudaFuncAttributeMaxDynamicSharedMemorySize, DSMEM_BYTES);
    cudaFuncSetAttribute(moe_gemm_kernel<D_FF, D_MODEL, false>,
                         cudaFuncAttributeMaxDynamicSharedMemorySize, DSMEM_BYTES);

    init_kernel<<<1, 32>>>();
    prep_kernel<<<6144, 256>>>(out, out_size, x, N, Wr, br, W1, W2);
    scan_kernel<<<1, 1>>>();

    dim3 g1(D_FF / BN, (N + BM - 1) / BM, NEXP);
    moe_gemm_kernel<D_MODEL, D_FF, true><<<g1, NTHREADS, DSMEM_BYTES>>>(b1, nullptr);

    dim3 g2(D_MODEL / BN, (N + BM - 1) / BM, NEXP);
    moe_gemm_kernel<D_FF, D_MODEL, false><<<g2, NTHREADS, DSMEM_BYTES>>>(b2, out);
}

// round 8
// speedup vs baseline: 1.0721x; 1.0721x over previous
#include <cuda_runtime.h>
#include <cuda_fp16.h>
#include <cstdint>
#include <math.h>

#define D_MODEL 1024
#define D_FF    4096
#define NEXP    8
#define MAXN    8192
#define HROWS   (2*MAXN + 256)

#define BM 128
#define BN 128
#define BK 32                      // halfs per stage along K
#define NTHREADS 128
#define A_STRIDE_B 80              // bytes per A smem row (64 data + 16 pad)
#define A_TILE_B (BM * A_STRIDE_B) // 10240
#define B_ROW_B  (BN * 2)          // 256 bytes per k-row (16 chunks)
#define B_TILE_B (BK * B_ROW_B)    // 8192
#define STAGE_B  (A_TILE_B + B_TILE_B)   // 18432
#define NSTAGE 4
#define DSMEM_BYTES (NSTAGE * STAGE_B)   // 73728 -> 2 CTAs/SM

// ---------------- scratch (static device globals; no allocation) ----------------
__device__ int    g_cnt[NEXP];
__device__ int    g_base[NEXP];
__device__ int    g_tok[NEXP * MAXN];
__device__ float  g_gate[NEXP * MAXN];
__device__ __half g_xh [(size_t)MAXN * D_MODEL];
__device__ __half g_W1h[(size_t)NEXP * D_MODEL * D_FF];
__device__ __half g_W2h[(size_t)NEXP * D_FF * D_MODEL];
__device__ __half g_Hh [(size_t)HROWS * D_FF];

// ---------------- helpers ----------------
__device__ __forceinline__ void mma_f16(float c[4], const uint32_t a[4], const uint32_t b[2]) {
    asm volatile(
        "mma.sync.aligned.m16n8k16.row.col.f32.f16.f16.f32 "
        "{%0,%1,%2,%3}, {%4,%5,%6,%7}, {%8,%9}, {%0,%1,%2,%3};"
        : "+f"(c[0]), "+f"(c[1]), "+f"(c[2]), "+f"(c[3])
        : "r"(a[0]), "r"(a[1]), "r"(a[2]), "r"(a[3]), "r"(b[0]), "r"(b[1]));
}
__device__ __forceinline__ void ldsm_x4(uint32_t& r0, uint32_t& r1, uint32_t& r2, uint32_t& r3,
                                        uint32_t saddr) {
    asm volatile("ldmatrix.sync.aligned.m8n8.x4.shared.b16 {%0,%1,%2,%3}, [%4];"
                 : "=r"(r0), "=r"(r1), "=r"(r2), "=r"(r3) : "r"(saddr));
}
__device__ __forceinline__ void ldsm_x4_t(uint32_t& r0, uint32_t& r1, uint32_t& r2, uint32_t& r3,
                                          uint32_t saddr) {
    asm volatile("ldmatrix.sync.aligned.m8n8.x4.trans.shared.b16 {%0,%1,%2,%3}, [%4];"
                 : "=r"(r0), "=r"(r1), "=r"(r2), "=r"(r3) : "r"(saddr));
}
__device__ __forceinline__ void cp16(uint32_t saddr, const void* g) {
    asm volatile("cp.async.cg.shared.global [%0], [%1], 16;" :: "r"(saddr), "l"(g) : "memory");
}
__device__ __forceinline__ void cp_commit() { asm volatile("cp.async.commit_group;" ::: "memory"); }
__device__ __forceinline__ void cp_wait2()  { asm volatile("cp.async.wait_group 2;" ::: "memory"); }

__device__ __forceinline__ float gelu_exact(float v) {
    return 0.5f * v * (1.0f + erff(v * 0.7071067811865476f));
}

// ---------------- tiny init: counters only ----------------
__global__ void init_kernel() {
    if (threadIdx.x < NEXP) g_cnt[threadIdx.x] = 0;
}

// ---------------- fused prep: router | zero out | half x | half W1/W2 ----------------
__global__ void prep_kernel(float* __restrict__ out, int nout,
                            const float* __restrict__ x, int N,
                            const float* __restrict__ Wr, const float* __restrict__ br,
                            const float* __restrict__ W1, const float* __restrict__ W2) {
    const int b = blockIdx.x;
    const int tid = threadIdx.x;

    if (b < 1024) {
        // ---- router: 8 warps per block, 1 token per warp ----
        int wg = b * 8 + (tid >> 5);
        int lane = tid & 31;
        if (wg >= N) return;
        const float* xr = x + (size_t)wg * D_MODEL;

        float acc[NEXP];
#pragma unroll
        for (int e = 0; e < NEXP; e++) acc[e] = 0.0f;
#pragma unroll
        for (int it = 0; it < D_MODEL / 128; it++) {
            int d = it * 128 + lane * 4;
            float4 xv = *reinterpret_cast<const float4*>(xr + d);
            const float xa[4] = { xv.x, xv.y, xv.z, xv.w };
#pragma unroll
            for (int q = 0; q < 4; q++) {
                const float4* w4 = reinterpret_cast<const float4*>(Wr + (size_t)(d + q) * NEXP);
                float4 w0 = w4[0], w1 = w4[1];
                acc[0] += xa[q] * w0.x; acc[1] += xa[q] * w0.y;
                acc[2] += xa[q] * w0.z; acc[3] += xa[q] * w0.w;
                acc[4] += xa[q] * w1.x; acc[5] += xa[q] * w1.y;
                acc[6] += xa[q] * w1.z; acc[7] += xa[q] * w1.w;
            }
        }
#pragma unroll
        for (int off = 16; off; off >>= 1)
#pragma unroll
            for (int e = 0; e < NEXP; e++)
                acc[e] += __shfl_xor_sync(0xffffffffu, acc[e], off);

        if (lane == 0) {
            float l[NEXP];
#pragma unroll
            for (int e = 0; e < NEXP; e++) l[e] = acc[e] + br[e];
            float m = l[0];
#pragma unroll
            for (int e = 1; e < NEXP; e++) m = fmaxf(m, l[e]);
            float p[NEXP], se = 0.0f;
#pragma unroll
            for (int e = 0; e < NEXP; e++) { p[e] = expf(l[e] - m); se += p[e]; }
            int i1 = 0; float v1 = p[0];
#pragma unroll
            for (int e = 1; e < NEXP; e++) if (p[e] > v1) { v1 = p[e]; i1 = e; }
            int i2 = -1; float v2 = -1.0f;
#pragma unroll
            for (int e = 0; e < NEXP; e++) if (e != i1 && p[e] > v2) { v2 = p[e]; i2 = e; }
            float p1 = v1 / se, p2 = v2 / se;
            float inv = 1.0f / (p1 + p2 + 1e-9f);
            float w1 = p1 * inv, w2 = p2 * inv;

            int pos = atomicAdd(&g_cnt[i1], 1);
            g_tok[i1 * MAXN + pos] = wg;  g_gate[i1 * MAXN + pos] = w1;
            pos = atomicAdd(&g_cnt[i2], 1);
            g_tok[i2 * MAXN + pos] = wg;  g_gate[i2 * MAXN + pos] = w2;
        }
    } else if (b < 1536) {
        int n4 = nout >> 2;
        float4 z = make_float4(0.f, 0.f, 0.f, 0.f);
        for (int i = (b - 1024) * 256 + tid; i < n4; i += 512 * 256)
            reinterpret_cast<float4*>(out)[i] = z;
    } else if (b < 2048) {
        int n4 = N * D_MODEL / 4;
        for (int i = (b - 1536) * 256 + tid; i < n4; i += 512 * 256) {
            float4 v = reinterpret_cast<const float4*>(x)[i];
            __half2 h0 = __floats2half2_rn(v.x, v.y);
            __half2 h1 = __floats2half2_rn(v.z, v.w);
            uint2 u = { *(uint32_t*)&h0, *(uint32_t*)&h1 };
            reinterpret_cast<uint2*>(g_xh)[i] = u;
        }
    } else {
        const int n4 = NEXP * D_MODEL * D_FF / 4;
        for (int i = (b - 2048) * 256 + tid; i < n4; i += 4096 * 256) {
            float4 v = reinterpret_cast<const float4*>(W1)[i];
            __half2 a0 = __floats2half2_rn(v.x, v.y);
            __half2 a1 = __floats2half2_rn(v.z, v.w);
            uint2 u = { *(uint32_t*)&a0, *(uint32_t*)&a1 };
            reinterpret_cast<uint2*>(g_W1h)[i] = u;
            float4 w = reinterpret_cast<const float4*>(W2)[i];
            __half2 b0 = __floats2half2_rn(w.x, w.y);
            __half2 b1 = __floats2half2_rn(w.z, w.w);
            uint2 t = { *(uint32_t*)&b0, *(uint32_t*)&b1 };
            reinterpret_cast<uint2*>(g_W2h)[i] = t;
        }
    }
}

__global__ void scan_kernel() {
    int b = 0;
#pragma unroll
    for (int e = 0; e < NEXP; e++) { g_base[e] = b; b += g_cnt[e]; }
}

// ---------------- grouped GEMM (fp16 mma.m16n8k16, CTA 128x128, 4 warps, warp 64x64) ----------------
template<int KD, int ND, bool PHASE1>
__global__ void __launch_bounds__(NTHREADS, 2)
moe_gemm_kernel(const float* __restrict__ bias, float* __restrict__ Out) {
    const int e  = blockIdx.z;
    const int Me = g_cnt[e];
    const int tm = blockIdx.y;
    if (tm * BM >= Me) return;
    const int tn   = blockIdx.x;
    const int base = g_base[e];

    extern __shared__ char smem[];
    const uint32_t sbase = (uint32_t)__cvta_generic_to_shared(smem);

    const int tid = threadIdx.x;
    const __half* Aglob = PHASE1 ? g_xh : g_Hh;
    const __half* We    = (PHASE1 ? g_W1h : g_W2h) + (size_t)e * KD * ND;

    // ---- A loader: 4 chunks of 16B per thread (128 rows x 4 chunks)
    const __half* agp[4]; uint32_t aso[4];
#pragma unroll
    for (int j = 0; j < 4; j++) {
        int cid = tid + NTHREADS * j;
        int row = cid >> 2, ch = cid & 3;
        int m = tm * BM + row;
        size_t arow;
        if (PHASE1) arow = (size_t)g_tok[e * MAXN + (m < Me ? m : 0)];
        else { long r = (long)base + m; if (r >= HROWS) r = 0; arow = (size_t)r; }
        agp[j] = Aglob + arow * KD + ch * 8;
        aso[j] = row * A_STRIDE_B + ch * 16;
    }
    // ---- B loader: 4 chunks of 16B per thread (32 krows x 16 chunks)
    const __half* bgp[4]; uint32_t bso[4];
#pragma unroll
    for (int j = 0; j < 4; j++) {
        int cid = tid + NTHREADS * j;
        int krow = cid >> 4, c = cid & 15;
        bgp[j] = We + (size_t)krow * ND + tn * BN + c * 8;
        bso[j] = A_TILE_B + krow * B_ROW_B + ((c ^ (krow & 7)) << 4);
    }

    constexpr int KT = KD / BK;
    const int warp = tid >> 5, lane = tid & 31;
    const int wr = warp >> 1, wc = warp & 1;   // 2x2 warp grid; warp tile 64x64

    uint32_t a_addr[4];
#pragma unroll
    for (int mt = 0; mt < 4; mt++) {
        int row = wr * 64 + mt * 16 + (lane & 15);
        a_addr[mt] = row * A_STRIDE_B + (lane >> 4) * 16;
    }
    uint32_t b_addr[2][4];
#pragma unroll
    for (int ks = 0; ks < 2; ks++)
#pragma unroll
        for (int nb = 0; nb < 4; nb++) {
            int krow = ks * 16 + (lane & 15);
            int nc = wc * 8 + nb * 2 + (lane >> 4);
            b_addr[ks][nb] = A_TILE_B + krow * B_ROW_B + ((nc ^ (krow & 7)) << 4);
        }

    float c[4][8][4];
#pragma unroll
    for (int i = 0; i < 4; i++)
#pragma unroll
        for (int j = 0; j < 8; j++)
#pragma unroll
            for (int k = 0; k < 4; k++) c[i][j][k] = 0.0f;

    // prologue: stages 0..2
#pragma unroll
    for (int s = 0; s < NSTAGE - 1; s++) {
        uint32_t sb = sbase + s * STAGE_B;
        size_t ko = (size_t)s * BK;
#pragma unroll
        for (int j = 0; j < 4; j++) cp16(sb + aso[j], agp[j] + ko);
#pragma unroll
        for (int j = 0; j < 4; j++) cp16(sb + bso[j], bgp[j] + ko * ND);
        cp_commit();
    }

    for (int kt = 0; kt < KT; kt++) {
        cp_wait2();
        __syncthreads();
        const uint32_t sb = sbase + (kt & (NSTAGE - 1)) * STAGE_B;

        // ---- batch ALL fragment loads for this k-tile (both ks halves) ----
        uint32_t af[2][4][4], bf[2][4][4];
#pragma unroll
        for (int ks = 0; ks < 2; ks++)
#pragma unroll
            for (int mt = 0; mt < 4; mt++)
                ldsm_x4(af[ks][mt][0], af[ks][mt][1], af[ks][mt][2], af[ks][mt][3],
                        sb + a_addr[mt] + ks * 32);
#pragma unroll
        for (int ks = 0; ks < 2; ks++)
#pragma unroll
            for (int nb = 0; nb < 4; nb++)
                ldsm_x4_t(bf[ks][nb][0], bf[ks][nb][1], bf[ks][nb][2], bf[ks][nb][3],
                          sb + b_addr[ks][nb]);

        // ---- prefetch next stage in the ldsm latency shadow ----
        if (kt + NSTAGE - 1 < KT) {
            int st = (kt + NSTAGE - 1) & (NSTAGE - 1);
            size_t ko = (size_t)(kt + NSTAGE - 1) * BK;
            uint32_t sp = sbase + st * STAGE_B;
#pragma unroll
            for (int j = 0; j < 4; j++) cp16(sp + aso[j], agp[j] + ko);
#pragma unroll
            for (int j = 0; j < 4; j++) cp16(sp + bso[j], bgp[j] + ko * ND);
        }
        cp_commit();

        // ---- uninterrupted MMA burst: 64 HMMAs ----
#pragma unroll
        for (int ks = 0; ks < 2; ks++)
#pragma unroll
            for (int mt = 0; mt < 4; mt++)
#pragma unroll
                for (int nb = 0; nb < 4; nb++) {
                    mma_f16(c[mt][nb * 2 + 0], af[ks][mt], &bf[ks][nb][0]);
                    mma_f16(c[mt][nb * 2 + 1], af[ks][mt], &bf[ks][nb][2]);
                }
    }

    // ---- epilogue ----
    const float* be = bias + (size_t)e * ND;
    const int bofs = tn * BN;
#pragma unroll
    for (int mt = 0; mt < 4; mt++) {
        int mrow = tm * BM + wr * 64 + mt * 16 + (lane >> 2);
#pragma unroll
        for (int half = 0; half < 2; half++) {
            int m = mrow + half * 8;
            if (m >= Me) continue;
            if (PHASE1) {
                __half* Hr = g_Hh + (size_t)(base + m) * ND + bofs;
#pragma unroll
                for (int nt = 0; nt < 8; nt++) {
                    int n = wc * 64 + nt * 8 + (lane & 3) * 2;
                    float v0 = c[mt][nt][half * 2 + 0] + be[bofs + n];
                    float v1 = c[mt][nt][half * 2 + 1] + be[bofs + n + 1];
                    __half2 h = __floats2half2_rn(gelu_exact(v0), gelu_exact(v1));
                    *reinterpret_cast<uint32_t*>(Hr + n) = *(uint32_t*)&h;
                }
            } else {
                int tok = g_tok[e * MAXN + m];
                float g = g_gate[e * MAXN + m];
                float* Or = Out + (size_t)tok * ND + bofs;
#pragma unroll
                for (int nt = 0; nt < 8; nt++) {
                    int n = wc * 64 + nt * 8 + (lane & 3) * 2;
                    atomicAdd(&Or[n],     g * (c[mt][nt][half * 2 + 0] + be[bofs + n]));
                    atomicAdd(&Or[n + 1], g * (c[mt][nt][half * 2 + 1] + be[bofs + n + 1]));
                }
            }
        }
    }
}

// ---------------- launch ----------------
extern "C" void kernel_launch(void* const* d_in, const int* in_sizes, int n_in,
                              void* d_out, int out_size) {
    const float* x  = (const float*)d_in[0];
    const float* Wr = (const float*)d_in[1];
    const float* br = (const float*)d_in[2];
    const float* W1 = (const float*)d_in[3];
    const float* b1 = (const float*)d_in[4];
    const float* W2 = (const float*)d_in[5];
    const float* b2 = (const float*)d_in[6];
    float* out = (float*)d_out;

    int N = in_sizes[0] / D_MODEL;   // 8192 tokens
    if (N > MAXN) N = MAXN;

    cudaFuncSetAttribute(moe_gemm_kernel<D_MODEL, D_FF, true>,
                         cudaFuncAttributeMaxDynamicSharedMemorySize, DSMEM_BYTES);
    cudaFuncSetAttribute(moe_gemm_kernel<D_FF, D_MODEL, false>,
                         cudaFuncAttributeMaxDynamicSharedMemorySize, DSMEM_BYTES);

    init_kernel<<<1, 32>>>();
    prep_kernel<<<6144, 256>>>(out, out_size, x, N, Wr, br, W1, W2);
    scan_kernel<<<1, 1>>>();

    dim3 g1(D_FF / BN, (N + BM - 1) / BM, NEXP);
    moe_gemm_kernel<D_MODEL, D_FF, true><<<g1, NTHREADS, DSMEM_BYTES>>>(b1, nullptr);

    dim3 g2(D_MODEL / BN, (N + BM - 1) / BM, NEXP);
    moe_gemm_kernel<D_FF, D_MODEL, false><<<g2, NTHREADS, DSMEM_BYTES>>>(b2, out);
}

// round 9
// speedup vs baseline: 1.0834x; 1.0105x over previous
#include <cuda_runtime.h>
#include <cuda_fp16.h>
#include <cstdint>
#include <math.h>

#define D_MODEL 1024
#define D_FF    4096
#define NEXP    8
#define MAXN    8192
#define HROWS   (2*MAXN + 256)

#define BM 128
#define BN 128
#define BK 32                      // halfs per stage along K
#define NTHREADS 128
#define A_STRIDE_B 80              // bytes per A smem row (64 data + 16 pad)
#define A_TILE_B (BM * A_STRIDE_B) // 10240
#define B_ROW_B  (BN * 2)          // 256 bytes per k-row (16 chunks)
#define B_TILE_B (BK * B_ROW_B)    // 8192
#define STAGE_B  (A_TILE_B + B_TILE_B)   // 18432
#define NSTAGE 6
#define DSMEM_BYTES (NSTAGE * STAGE_B)   // 110592 -> 2 CTAs/SM

// ---------------- scratch (static device globals; no allocation) ----------------
__device__ int    g_cnt[NEXP];
__device__ int    g_base[NEXP];
__device__ int    g_tok[NEXP * MAXN];
__device__ float  g_gate[NEXP * MAXN];
__device__ __half g_xh [(size_t)MAXN * D_MODEL];
__device__ __half g_W1h[(size_t)NEXP * D_MODEL * D_FF];
__device__ __half g_W2h[(size_t)NEXP * D_FF * D_MODEL];
__device__ __half g_Hh [(size_t)HROWS * D_FF];

// ---------------- helpers ----------------
__device__ __forceinline__ void mma_f16(float c[4], const uint32_t a[4], const uint32_t b[2]) {
    asm volatile(
        "mma.sync.aligned.m16n8k16.row.col.f32.f16.f16.f32 "
        "{%0,%1,%2,%3}, {%4,%5,%6,%7}, {%8,%9}, {%0,%1,%2,%3};"
        : "+f"(c[0]), "+f"(c[1]), "+f"(c[2]), "+f"(c[3])
        : "r"(a[0]), "r"(a[1]), "r"(a[2]), "r"(a[3]), "r"(b[0]), "r"(b[1]));
}
__device__ __forceinline__ void ldsm_x4(uint32_t& r0, uint32_t& r1, uint32_t& r2, uint32_t& r3,
                                        uint32_t saddr) {
    asm volatile("ldmatrix.sync.aligned.m8n8.x4.shared.b16 {%0,%1,%2,%3}, [%4];"
                 : "=r"(r0), "=r"(r1), "=r"(r2), "=r"(r3) : "r"(saddr));
}
__device__ __forceinline__ void ldsm_x4_t(uint32_t& r0, uint32_t& r1, uint32_t& r2, uint32_t& r3,
                                          uint32_t saddr) {
    asm volatile("ldmatrix.sync.aligned.m8n8.x4.trans.shared.b16 {%0,%1,%2,%3}, [%4];"
                 : "=r"(r0), "=r"(r1), "=r"(r2), "=r"(r3) : "r"(saddr));
}
__device__ __forceinline__ void cp16(uint32_t saddr, const void* g) {
    asm volatile("cp.async.cg.shared.global [%0], [%1], 16;" :: "r"(saddr), "l"(g) : "memory");
}
__device__ __forceinline__ void cp_commit() { asm volatile("cp.async.commit_group;" ::: "memory"); }
__device__ __forceinline__ void cp_wait2()  { asm volatile("cp.async.wait_group 2;" ::: "memory"); }

__device__ __forceinline__ float gelu_exact(float v) {
    return 0.5f * v * (1.0f + erff(v * 0.7071067811865476f));
}

// ---------------- tiny init: counters only ----------------
__global__ void init_kernel() {
    if (threadIdx.x < NEXP) g_cnt[threadIdx.x] = 0;
}

// ---------------- fused prep: router | zero out | half x | half W1/W2 ----------------
__global__ void prep_kernel(float* __restrict__ out, int nout,
                            const float* __restrict__ x, int N,
                            const float* __restrict__ Wr, const float* __restrict__ br,
                            const float* __restrict__ W1, const float* __restrict__ W2) {
    const int b = blockIdx.x;
    const int tid = threadIdx.x;

    if (b < 1024) {
        // ---- router: 8 warps per block, 1 token per warp ----
        int wg = b * 8 + (tid >> 5);
        int lane = tid & 31;
        if (wg >= N) return;
        const float* xr = x + (size_t)wg * D_MODEL;

        float acc[NEXP];
#pragma unroll
        for (int e = 0; e < NEXP; e++) acc[e] = 0.0f;
#pragma unroll
        for (int it = 0; it < D_MODEL / 128; it++) {
            int d = it * 128 + lane * 4;
            float4 xv = *reinterpret_cast<const float4*>(xr + d);
            const float xa[4] = { xv.x, xv.y, xv.z, xv.w };
#pragma unroll
            for (int q = 0; q < 4; q++) {
                const float4* w4 = reinterpret_cast<const float4*>(Wr + (size_t)(d + q) * NEXP);
                float4 w0 = w4[0], w1 = w4[1];
                acc[0] += xa[q] * w0.x; acc[1] += xa[q] * w0.y;
                acc[2] += xa[q] * w0.z; acc[3] += xa[q] * w0.w;
                acc[4] += xa[q] * w1.x; acc[5] += xa[q] * w1.y;
                acc[6] += xa[q] * w1.z; acc[7] += xa[q] * w1.w;
            }
        }
#pragma unroll
        for (int off = 16; off; off >>= 1)
#pragma unroll
            for (int e = 0; e < NEXP; e++)
                acc[e] += __shfl_xor_sync(0xffffffffu, acc[e], off);

        if (lane == 0) {
            float l[NEXP];
#pragma unroll
            for (int e = 0; e < NEXP; e++) l[e] = acc[e] + br[e];
            float m = l[0];
#pragma unroll
            for (int e = 1; e < NEXP; e++) m = fmaxf(m, l[e]);
            float p[NEXP], se = 0.0f;
#pragma unroll
            for (int e = 0; e < NEXP; e++) { p[e] = expf(l[e] - m); se += p[e]; }
            int i1 = 0; float v1 = p[0];
#pragma unroll
            for (int e = 1; e < NEXP; e++) if (p[e] > v1) { v1 = p[e]; i1 = e; }
            int i2 = -1; float v2 = -1.0f;
#pragma unroll
            for (int e = 0; e < NEXP; e++) if (e != i1 && p[e] > v2) { v2 = p[e]; i2 = e; }
            float p1 = v1 / se, p2 = v2 / se;
            float inv = 1.0f / (p1 + p2 + 1e-9f);
            float w1 = p1 * inv, w2 = p2 * inv;

            int pos = atomicAdd(&g_cnt[i1], 1);
            g_tok[i1 * MAXN + pos] = wg;  g_gate[i1 * MAXN + pos] = w1;
            pos = atomicAdd(&g_cnt[i2], 1);
            g_tok[i2 * MAXN + pos] = wg;  g_gate[i2 * MAXN + pos] = w2;
        }
    } else if (b < 1536) {
        int n4 = nout >> 2;
        float4 z = make_float4(0.f, 0.f, 0.f, 0.f);
        for (int i = (b - 1024) * 256 + tid; i < n4; i += 512 * 256)
            reinterpret_cast<float4*>(out)[i] = z;
    } else if (b < 2048) {
        int n4 = N * D_MODEL / 4;
        for (int i = (b - 1536) * 256 + tid; i < n4; i += 512 * 256) {
            float4 v = reinterpret_cast<const float4*>(x)[i];
            __half2 h0 = __floats2half2_rn(v.x, v.y);
            __half2 h1 = __floats2half2_rn(v.z, v.w);
            uint2 u = { *(uint32_t*)&h0, *(uint32_t*)&h1 };
            reinterpret_cast<uint2*>(g_xh)[i] = u;
        }
    } else {
        const int n4 = NEXP * D_MODEL * D_FF / 4;
        for (int i = (b - 2048) * 256 + tid; i < n4; i += 4096 * 256) {
            float4 v = reinterpret_cast<const float4*>(W1)[i];
            __half2 a0 = __floats2half2_rn(v.x, v.y);
            __half2 a1 = __floats2half2_rn(v.z, v.w);
            uint2 u = { *(uint32_t*)&a0, *(uint32_t*)&a1 };
            reinterpret_cast<uint2*>(g_W1h)[i] = u;
            float4 w = reinterpret_cast<const float4*>(W2)[i];
            __half2 b0 = __floats2half2_rn(w.x, w.y);
            __half2 b1 = __floats2half2_rn(w.z, w.w);
            uint2 t = { *(uint32_t*)&b0, *(uint32_t*)&b1 };
            reinterpret_cast<uint2*>(g_W2h)[i] = t;
        }
    }
}

__global__ void scan_kernel() {
    int b = 0;
#pragma unroll
    for (int e = 0; e < NEXP; e++) { g_base[e] = b; b += g_cnt[e]; }
}

// ---------------- grouped GEMM: 2 k-tiles per barrier, 6-stage pipeline ----------------
template<int KD, int ND, bool PHASE1>
__global__ void __launch_bounds__(NTHREADS, 2)
moe_gemm_kernel(const float* __restrict__ bias, float* __restrict__ Out) {
    const int e  = blockIdx.z;
    const int Me = g_cnt[e];
    const int tm = blockIdx.y;
    if (tm * BM >= Me) return;
    const int tn   = blockIdx.x;
    const int base = g_base[e];

    extern __shared__ char smem[];
    const uint32_t sbase = (uint32_t)__cvta_generic_to_shared(smem);

    const int tid = threadIdx.x;
    const __half* Aglob = PHASE1 ? g_xh : g_Hh;
    const __half* We    = (PHASE1 ? g_W1h : g_W2h) + (size_t)e * KD * ND;

    // ---- A loader: 4 chunks of 16B per thread (128 rows x 4 chunks)
    const __half* agp[4]; uint32_t aso[4];
#pragma unroll
    for (int j = 0; j < 4; j++) {
        int cid = tid + NTHREADS * j;
        int row = cid >> 2, ch = cid & 3;
        int m = tm * BM + row;
        size_t arow;
        if (PHASE1) arow = (size_t)g_tok[e * MAXN + (m < Me ? m : 0)];
        else { long r = (long)base + m; if (r >= HROWS) r = 0; arow = (size_t)r; }
        agp[j] = Aglob + arow * KD + ch * 8;
        aso[j] = row * A_STRIDE_B + ch * 16;
    }
    // ---- B loader: 4 chunks of 16B per thread (32 krows x 16 chunks)
    const __half* bgp[4]; uint32_t bso[4];
#pragma unroll
    for (int j = 0; j < 4; j++) {
        int cid = tid + NTHREADS * j;
        int krow = cid >> 4, c = cid & 15;
        bgp[j] = We + (size_t)krow * ND + tn * BN + c * 8;
        bso[j] = A_TILE_B + krow * B_ROW_B + ((c ^ (krow & 7)) << 4);
    }

    constexpr int KT = KD / BK;        // 32 (GEMM1) / 128 (GEMM2); even
    const int warp = tid >> 5, lane = tid & 31;
    const int wr = warp >> 1, wc = warp & 1;   // 2x2 warp grid; warp tile 64x64

    uint32_t a_addr[4];
#pragma unroll
    for (int mt = 0; mt < 4; mt++) {
        int row = wr * 64 + mt * 16 + (lane & 15);
        a_addr[mt] = row * A_STRIDE_B + (lane >> 4) * 16;
    }
    uint32_t b_addr[2][4];
#pragma unroll
    for (int ks = 0; ks < 2; ks++)
#pragma unroll
        for (int nb = 0; nb < 4; nb++) {
            int krow = ks * 16 + (lane & 15);
            int nc = wc * 8 + nb * 2 + (lane >> 4);
            b_addr[ks][nb] = A_TILE_B + krow * B_ROW_B + ((nc ^ (krow & 7)) << 4);
        }

    float c[4][8][4];
#pragma unroll
    for (int i = 0; i < 4; i++)
#pragma unroll
        for (int j = 0; j < 8; j++)
#pragma unroll
            for (int k = 0; k < 4; k++) c[i][j][k] = 0.0f;

    // prologue: stages 0..3 (4 groups)
#pragma unroll
    for (int s = 0; s < 4; s++) {
        uint32_t sb = sbase + s * STAGE_B;
        size_t ko = (size_t)s * BK;
#pragma unroll
        for (int j = 0; j < 4; j++) cp16(sb + aso[j], agp[j] + ko);
#pragma unroll
        for (int j = 0; j < 4; j++) cp16(sb + bso[j], bgp[j] + ko * ND);
        cp_commit();
    }

    int slot = 0;   // stage slot of the first k-tile of this iteration
    for (int kt = 0; kt < KT; kt += 2) {
        cp_wait2();            // both stages of this iteration complete
        __syncthreads();

        const int slot1 = (slot + 1 == NSTAGE) ? 0 : slot + 1;
        const uint32_t sb0 = sbase + slot * STAGE_B;
        const uint32_t sb1 = sbase + slot1 * STAGE_B;

        // ======== k-tile kt (slot) ========
        uint32_t af[2][4][4], bf[2][4][4];
#pragma unroll
        for (int ks = 0; ks < 2; ks++)
#pragma unroll
            for (int mt = 0; mt < 4; mt++)
                ldsm_x4(af[ks][mt][0], af[ks][mt][1], af[ks][mt][2], af[ks][mt][3],
                        sb0 + a_addr[mt] + ks * 32);
#pragma unroll
        for (int ks = 0; ks < 2; ks++)
#pragma unroll
            for (int nb = 0; nb < 4; nb++)
                ldsm_x4_t(bf[ks][nb][0], bf[ks][nb][1], bf[ks][nb][2], bf[ks][nb][3],
                          sb0 + b_addr[ks][nb]);

        // prefetch stage kt+4 in the ldsm shadow
        {
            int pk = kt + 4;
            if (pk < KT) {
                int st = slot + 4; if (st >= NSTAGE) st -= NSTAGE;
                uint32_t sp = sbase + st * STAGE_B;
                size_t ko = (size_t)pk * BK;
#pragma unroll
                for (int j = 0; j < 4; j++) cp16(sp + aso[j], agp[j] + ko);
#pragma unroll
                for (int j = 0; j < 4; j++) cp16(sp + bso[j], bgp[j] + ko * ND);
            }
            cp_commit();
        }

#pragma unroll
        for (int ks = 0; ks < 2; ks++)
#pragma unroll
            for (int mt = 0; mt < 4; mt++)
#pragma unroll
                for (int nb = 0; nb < 4; nb++) {
                    mma_f16(c[mt][nb * 2 + 0], af[ks][mt], &bf[ks][nb][0]);
                    mma_f16(c[mt][nb * 2 + 1], af[ks][mt], &bf[ks][nb][2]);
                }

        // ======== k-tile kt+1 (slot1) ========
#pragma unroll
        for (int ks = 0; ks < 2; ks++)
#pragma unroll
            for (int mt = 0; mt < 4; mt++)
                ldsm_x4(af[ks][mt][0], af[ks][mt][1], af[ks][mt][2], af[ks][mt][3],
                        sb1 + a_addr[mt] + ks * 32);
#pragma unroll
        for (int ks = 0; ks < 2; ks++)
#pragma unroll
            for (int nb = 0; nb < 4; nb++)
                ldsm_x4_t(bf[ks][nb][0], bf[ks][nb][1], bf[ks][nb][2], bf[ks][nb][3],
                          sb1 + b_addr[ks][nb]);

        // prefetch stage kt+5 in the ldsm shadow
        {
            int pk = kt + 5;
            if (pk < KT) {
                int st = slot + 5; if (st >= NSTAGE) st -= NSTAGE;
                uint32_t sp = sbase + st * STAGE_B;
                size_t ko = (size_t)pk * BK;
#pragma unroll
                for (int j = 0; j < 4; j++) cp16(sp + aso[j], agp[j] + ko);
#pragma unroll
                for (int j = 0; j < 4; j++) cp16(sp + bso[j], bgp[j] + ko * ND);
            }
            cp_commit();
        }

#pragma unroll
        for (int ks = 0; ks < 2; ks++)
#pragma unroll
            for (int mt = 0; mt < 4; mt++)
#pragma unroll
                for (int nb = 0; nb < 4; nb++) {
                    mma_f16(c[mt][nb * 2 + 0], af[ks][mt], &bf[ks][nb][0]);
                    mma_f16(c[mt][nb * 2 + 1], af[ks][mt], &bf[ks][nb][2]);
                }

        slot += 2; if (slot >= NSTAGE) slot -= NSTAGE;
    }

    // ---- epilogue ----
    const float* be = bias + (size_t)e * ND;
    const int bofs = tn * BN;
#pragma unroll
    for (int mt = 0; mt < 4; mt++) {
        int mrow = tm * BM + wr * 64 + mt * 16 + (lane >> 2);
#pragma unroll
        for (int half = 0; half < 2; half++) {
            int m = mrow + half * 8;
            if (m >= Me) continue;
            if (PHASE1) {
                __half* Hr = g_Hh + (size_t)(base + m) * ND + bofs;
#pragma unroll
                for (int nt = 0; nt < 8; nt++) {
                    int n = wc * 64 + nt * 8 + (lane & 3) * 2;
                    float v0 = c[mt][nt][half * 2 + 0] + be[bofs + n];
                    float v1 = c[mt][nt][half * 2 + 1] + be[bofs + n + 1];
                    __half2 h = __floats2half2_rn(gelu_exact(v0), gelu_exact(v1));
                    *reinterpret_cast<uint32_t*>(Hr + n) = *(uint32_t*)&h;
                }
            } else {
                int tok = g_tok[e * MAXN + m];
                float g = g_gate[e * MAXN + m];
                float* Or = Out + (size_t)tok * ND + bofs;
#pragma unroll
                for (int nt = 0; nt < 8; nt++) {
                    int n = wc * 64 + nt * 8 + (lane & 3) * 2;
                    atomicAdd(&Or[n],     g * (c[mt][nt][half * 2 + 0] + be[bofs + n]));
                    atomicAdd(&Or[n + 1], g * (c[mt][nt][half * 2 + 1] + be[bofs + n + 1]));
                }
            }
        }
    }
}

// ---------------- launch ----------------
extern "C" void kernel_launch(void* const* d_in, const int* in_sizes, int n_in,
                              void* d_out, int out_size) {
    const float* x  = (const float*)d_in[0];
    const float* Wr = (const float*)d_in[1];
    const float* br = (const float*)d_in[2];
    const float* W1 = (const float*)d_in[3];
    const float* b1 = (const float*)d_in[4];
    const float* W2 = (const float*)d_in[5];
    const float* b2 = (const float*)d_in[6];
    float* out = (float*)d_out;

    int N = in_sizes[0] / D_MODEL;   // 8192 tokens
    if (N > MAXN) N = MAXN;

    cudaFuncSetAttribute(moe_gemm_kernel<D_MODEL, D_FF, true>,
                         cudaFuncAttributeMaxDynamicSharedMemorySize, DSMEM_BYTES);
    cudaFuncSetAttribute(moe_gemm_kernel<D_FF, D_MODEL, false>,
                         cudaFuncAttributeMaxDynamicSharedMemorySize, DSMEM_BYTES);

    init_kernel<<<1, 32>>>();
    prep_kernel<<<6144, 256>>>(out, out_size, x, N, Wr, br, W1, W2);
    scan_kernel<<<1, 1>>>();

    dim3 g1(D_FF / BN, (N + BM - 1) / BM, NEXP);
    moe_gemm_kernel<D_MODEL, D_FF, true><<<g1, NTHREADS, DSMEM_BYTES>>>(b1, nullptr);

    dim3 g2(D_MODEL / BN, (N + BM - 1) / BM, NEXP);
    moe_gemm_kernel<D_FF, D_MODEL, false><<<g2, NTHREADS, DSMEM_BYTES>>>(b2, out);
}